// round 3
// baseline (speedup 1.0000x reference)
#include <cuda_runtime.h>
#include <math.h>

#define CDIM  256
#define HEADS 8
#define TBLK  512               // tokens per CTA
#define NTB   256               // 131072 / TBLK token blocks (128 per batch)

// Scratch: small static device arrays only (~34 MB total)
__device__ float g_Wh[HEADS * CDIM * 128];          // [h][k][col] col<64: Wx@Wslice fold, col>=64: Wfx
__device__ float g_bh[HEADS * 128];                 // matching bias
__device__ float g_Mp[(size_t)NTB * HEADS * 4096];  // per (tb,h) partial 64x64
__device__ float g_Np[NTB * HEADS * 64];            // per (tb,h) partial slice-mass

// ---------------------------------------------------------------------------
// K1: fold Wslice into Wx per head, concat with Wfx head slice. Tiny.
// ---------------------------------------------------------------------------
__global__ __launch_bounds__(256) void k_fold(
    const float* __restrict__ Wx,  const float* __restrict__ bx,
    const float* __restrict__ Wfx, const float* __restrict__ bfx,
    const float* __restrict__ Ws,  const float* __restrict__ bs)
{
    int j = blockIdx.x * 256 + threadIdx.x;    // 0 .. 8*256*128-1
    int h   = j >> 15;
    int k   = (j >> 7) & 255;
    int col = j & 127;
    float v;
    if (col < 64) {
        float acc = 0.f;
        #pragma unroll 8
        for (int d = 0; d < 64; d++)
            acc += Wx[k * 512 + h * 64 + d] * Ws[d * 64 + col];
        v = acc;
        if (k == 0) {
            float bacc = bs[col];
            for (int d = 0; d < 64; d++)
                bacc += bx[h * 64 + d] * Ws[d * 64 + col];
            g_bh[h * 128 + col] = bacc;
        }
    } else {
        v = Wfx[k * 512 + h * 64 + (col - 64)];
        if (k == 0) g_bh[h * 128 + col] = bfx[h * 64 + (col - 64)];
    }
    g_Wh[j] = v;                                // j == (h*256 + k)*128 + col
}

// ---------------------------------------------------------------------------
// K2: fully fused. CTA = (head h, 512-token block tb).
//  Per 64-token sub-tile:
//    front GEMM  Y(64x128) = x_sub(64x256) @ Wh(256x128)   (4x8 thread tiles)
//    cols 0..63  -> temperature softmax (8-lane butterflies) -> ws[64][64]
//    cols 64..127-> +bias -> fs[64][64]
//    agg         M(64x64) += ws^T @ fs  (register 4x4 tiles), norms += colsum(ws)
//  Partials written deterministically to g_Mp / g_Np.
// ---------------------------------------------------------------------------
__global__ __launch_bounds__(256, 2) void k_main(
    const float* __restrict__ x, const float* __restrict__ temp)
{
    __shared__ float As[8][64];
    __shared__ float Bs[8][128];
    __shared__ float ws[64][64];
    __shared__ float fs[64][64];

    const int h   = blockIdx.x;
    const int tb  = blockIdx.y;
    const int tid = threadIdx.x;
    const int tr = tid >> 4, tc = tid & 15;       // 16x16 thread grid
    const int br = tid >> 5, bc = (tid & 31) * 4; // B stage: row 0..7, col 0..124
    const int lm = tid >> 1, lq = (tid & 1) * 4;  // A stage (tid<128): row 0..63

    const float* Wh = &g_Wh[h * CDIM * 128];

    float tv = temp[h];
    tv = fminf(fmaxf(tv, 0.5f), 5.0f);
    const float inv = 1.0f / tv;
    float bias[8];
    #pragma unroll
    for (int j = 0; j < 8; j++) bias[j] = g_bh[h * 128 + tc * 8 + j];

    float agg[4][4];
    #pragma unroll
    for (int u = 0; u < 4; u++)
        #pragma unroll
        for (int v = 0; v < 4; v++) agg[u][v] = 0.f;
    float nacc[4] = {0.f, 0.f, 0.f, 0.f};

    for (int sub = 0; sub < 8; sub++) {
        const float* xg = x + (size_t)(tb * TBLK + sub * 64) * CDIM;

        float acc[4][8];
        #pragma unroll
        for (int i = 0; i < 4; i++)
            #pragma unroll
            for (int j = 0; j < 8; j++) acc[i][j] = 0.f;

        for (int kb = 0; kb < 32; kb++) {
            if (tid < 128) {
                float4 va = *(const float4*)(xg + (size_t)lm * CDIM + kb * 8 + lq);
                As[lq + 0][lm] = va.x; As[lq + 1][lm] = va.y;
                As[lq + 2][lm] = va.z; As[lq + 3][lm] = va.w;
            }
            *(float4*)&Bs[br][bc] = *(const float4*)(&Wh[(kb * 8 + br) * 128 + bc]);
            __syncthreads();
            #pragma unroll
            for (int k = 0; k < 8; k++) {
                float a[4], b[8];
                *(float4*)&a[0] = *(const float4*)&As[k][tr * 4];
                *(float4*)&b[0] = *(const float4*)&Bs[k][tc * 8];
                *(float4*)&b[4] = *(const float4*)&Bs[k][tc * 8 + 4];
                #pragma unroll
                for (int i = 0; i < 4; i++)
                    #pragma unroll
                    for (int j = 0; j < 8; j++)
                        acc[i][j] = fmaf(a[i], b[j], acc[i][j]);
            }
            __syncthreads();
        }

        // Epilogue. Logit lanes are tc<8 <=> lane bit3 == 0 -> lanes {0-7,16-23}
        // of each warp: shuffle mask 0x00FF00FF, xor 1/2/4 stays in-group.
        if (tc < 8) {
            #pragma unroll
            for (int i = 0; i < 4; i++) {
                float v[8];
                float mx = -1e30f;
                #pragma unroll
                for (int j = 0; j < 8; j++) {
                    v[j] = (acc[i][j] + bias[j]) * inv;
                    mx = fmaxf(mx, v[j]);
                }
                mx = fmaxf(mx, __shfl_xor_sync(0x00FF00FFu, mx, 1));
                mx = fmaxf(mx, __shfl_xor_sync(0x00FF00FFu, mx, 2));
                mx = fmaxf(mx, __shfl_xor_sync(0x00FF00FFu, mx, 4));
                float sum = 0.f;
                #pragma unroll
                for (int j = 0; j < 8; j++) {
                    v[j] = __expf(v[j] - mx);
                    sum += v[j];
                }
                sum += __shfl_xor_sync(0x00FF00FFu, sum, 1);
                sum += __shfl_xor_sync(0x00FF00FFu, sum, 2);
                sum += __shfl_xor_sync(0x00FF00FFu, sum, 4);
                const float rs = 1.0f / sum;
                float* dst = &ws[tr * 4 + i][tc * 8];
                *(float4*)(dst + 0) = make_float4(v[0]*rs, v[1]*rs, v[2]*rs, v[3]*rs);
                *(float4*)(dst + 4) = make_float4(v[4]*rs, v[5]*rs, v[6]*rs, v[7]*rs);
            }
        } else {
            #pragma unroll
            for (int i = 0; i < 4; i++) {
                float* dst = &fs[tr * 4 + i][(tc - 8) * 8];
                *(float4*)(dst + 0) = make_float4(acc[i][0]+bias[0], acc[i][1]+bias[1],
                                                  acc[i][2]+bias[2], acc[i][3]+bias[3]);
                *(float4*)(dst + 4) = make_float4(acc[i][4]+bias[4], acc[i][5]+bias[5],
                                                  acc[i][6]+bias[6], acc[i][7]+bias[7]);
            }
        }
        __syncthreads();

        // Aggregate: M[s][d] += sum_n ws[n][s] * fs[n][d]
        #pragma unroll 4
        for (int n = 0; n < 64; n++) {
            float a[4], b[4];
            *(float4*)&a[0] = *(const float4*)&ws[n][tr * 4];
            *(float4*)&b[0] = *(const float4*)&fs[n][tc * 4];
            if (tc == 0) {
                nacc[0] += a[0]; nacc[1] += a[1];
                nacc[2] += a[2]; nacc[3] += a[3];
            }
            #pragma unroll
            for (int u = 0; u < 4; u++)
                #pragma unroll
                for (int v = 0; v < 4; v++)
                    agg[u][v] = fmaf(a[u], b[v], agg[u][v]);
        }
        __syncthreads();
    }

    float* Mp = &g_Mp[((size_t)tb * HEADS + h) * 4096];
    #pragma unroll
    for (int u = 0; u < 4; u++)
        *(float4*)&Mp[(tr * 4 + u) * 64 + tc * 4] =
            make_float4(agg[u][0], agg[u][1], agg[u][2], agg[u][3]);
    if (tc == 0) {
        float* Np = &g_Np[(tb * HEADS + h) * 64];
        #pragma unroll
        for (int u = 0; u < 4; u++) Np[tr * 4 + u] = nacc[u];
    }
}

// ---------------------------------------------------------------------------
// K3: reduce the 128 per-batch token-block partials, divide by (mass + 0.01).
// ---------------------------------------------------------------------------
__global__ __launch_bounds__(256) void k_final(float* __restrict__ out)
{
    int i = blockIdx.x * 256 + threadIdx.x;    // ((b*8+h)*64+s)*64+d
    int bh = i >> 12;
    int b = bh >> 3, h = bh & 7;
    int s = (i >> 6) & 63;
    float m = 0.f, nn = 0.f;
    for (int t = 0; t < 128; t++) {
        size_t base = (size_t)(b * 128 + t) * HEADS + h;
        m  += g_Mp[base * 4096 + (i & 4095)];
        nn += g_Np[base * 64 + s];
    }
    out[i] = m / (nn + 0.01f);
}

// ---------------------------------------------------------------------------
extern "C" void kernel_launch(void* const* d_in, const int* in_sizes, int n_in,
                              void* d_out, int out_size)
{
    const float* x    = (const float*)d_in[0];
    const float* Wx   = (const float*)d_in[1];
    const float* bx   = (const float*)d_in[2];
    const float* Wfx  = (const float*)d_in[3];
    const float* bfx  = (const float*)d_in[4];
    const float* Ws   = (const float*)d_in[5];
    const float* bs   = (const float*)d_in[6];
    const float* temp = (const float*)d_in[7];
    (void)in_sizes; (void)n_in; (void)out_size;

    k_fold<<<1024, 256>>>(Wx, bx, Wfx, bfx, Ws, bs);
    k_main<<<dim3(HEADS, NTB), 256>>>(x, temp);
    k_final<<<256, 256>>>((float*)d_out);
}

// round 4
// speedup vs baseline: 1.0175x; 1.0175x over previous
#include <cuda_runtime.h>
#include <math.h>

#define CDIM  256
#define HEADS 8
#define TBLK  512               // tokens per CTA
#define NTB   256               // 131072 / TBLK token blocks (128 per batch)

typedef unsigned long long u64;

// fma.rn.f32x2: packed dual fp32 FMA (sm_103a). acc = a2*b2 + acc (elementwise)
#define FFMA2(acc, a2, b2) \
    asm("fma.rn.f32x2 %0, %1, %2, %0;" : "+l"(acc) : "l"(a2), "l"(b2))
#define PACK2(out, x) \
    asm("mov.b64 %0, {%1, %1};" : "=l"(out) : "f"(x))
#define UNPACK2(lo, hi, in) \
    asm("mov.b64 {%0, %1}, %2;" : "=f"(lo), "=f"(hi) : "l"(in))

// Scratch (static device memory only, ~34 MB)
__device__ float g_Wh[HEADS * CDIM * 128];          // [h][k][col] col<64: Wx@Wslice fold, col>=64: Wfx
__device__ float g_bh[HEADS * 128];
__device__ float g_Mp[(size_t)NTB * HEADS * 4096];  // per (tb,h) partial 64x64
__device__ float g_Np[NTB * HEADS * 64];            // per (tb,h) partial slice-mass

// ---------------------------------------------------------------------------
// K1: fold Wslice into Wx per head, concat with Wfx head slice. Tiny.
// ---------------------------------------------------------------------------
__global__ __launch_bounds__(256) void k_fold(
    const float* __restrict__ Wx,  const float* __restrict__ bx,
    const float* __restrict__ Wfx, const float* __restrict__ bfx,
    const float* __restrict__ Ws,  const float* __restrict__ bs)
{
    int j = blockIdx.x * 256 + threadIdx.x;    // 0 .. 8*256*128-1
    int h   = j >> 15;
    int k   = (j >> 7) & 255;
    int col = j & 127;
    float v;
    if (col < 64) {
        float acc = 0.f;
        #pragma unroll 8
        for (int d = 0; d < 64; d++)
            acc += Wx[k * 512 + h * 64 + d] * Ws[d * 64 + col];
        v = acc;
        if (k == 0) {
            float bacc = bs[col];
            for (int d = 0; d < 64; d++)
                bacc += bx[h * 64 + d] * Ws[d * 64 + col];
            g_bh[h * 128 + col] = bacc;
        }
    } else {
        v = Wfx[k * 512 + h * 64 + (col - 64)];
        if (k == 0) g_bh[h * 128 + col] = bfx[h * 64 + (col - 64)];
    }
    g_Wh[j] = v;
}

// ---------------------------------------------------------------------------
// K2: fused front GEMM + softmax + aggregation. FFMA2 mainloop, 2-stage smem.
// ---------------------------------------------------------------------------
__global__ __launch_bounds__(256, 2) void k_main(
    const float* __restrict__ x, const float* __restrict__ temp)
{
    __shared__ float As[2][8][64];
    __shared__ float Bs[2][8][128];
    __shared__ float ws[64][64];
    __shared__ float fs[64][64];

    const int h   = blockIdx.x;
    const int tb  = blockIdx.y;
    const int tid = threadIdx.x;
    const int tr = tid >> 4, tc = tid & 15;       // 16x16 thread grid
    const int br = tid >> 5, bc = (tid & 31) * 4; // B stage: row 0..7, col
    const int lm = tid >> 1, lq = (tid & 1) * 4;  // A stage (tid<128): row 0..63

    const float* Wh = &g_Wh[h * CDIM * 128];

    float tv = temp[h];
    tv = fminf(fmaxf(tv, 0.5f), 5.0f);
    const float inv = 1.0f / tv;
    float bias[8];
    #pragma unroll
    for (int j = 0; j < 8; j++) bias[j] = g_bh[h * 128 + tc * 8 + j];

    u64 agg2[4][2];                // packed pairs over d
    #pragma unroll
    for (int u = 0; u < 4; u++) { agg2[u][0] = 0ull; agg2[u][1] = 0ull; }
    float nacc[4] = {0.f, 0.f, 0.f, 0.f};

    for (int sub = 0; sub < 8; sub++) {
        const float* xg = x + (size_t)(tb * TBLK + sub * 64) * CDIM;

        u64 acc2[4][4];            // 4 rows x 4 col-pairs (8 cols)
        #pragma unroll
        for (int i = 0; i < 4; i++)
            #pragma unroll
            for (int jp = 0; jp < 4; jp++) acc2[i][jp] = 0ull;

        // prologue: stage kb=0 into buffer 0
        if (tid < 128) {
            float4 va = *(const float4*)(xg + (size_t)lm * CDIM + lq);
            As[0][lq + 0][lm] = va.x; As[0][lq + 1][lm] = va.y;
            As[0][lq + 2][lm] = va.z; As[0][lq + 3][lm] = va.w;
        }
        *(float4*)&Bs[0][br][bc] = *(const float4*)(&Wh[br * 128 + bc]);
        __syncthreads();

        float4 va_n, vb_n;
        for (int kb = 0; kb < 32; kb++) {
            const int cur = kb & 1;
            if (kb < 31) {
                if (tid < 128)
                    va_n = *(const float4*)(xg + (size_t)lm * CDIM + (kb + 1) * 8 + lq);
                vb_n = *(const float4*)(&Wh[((kb + 1) * 8 + br) * 128 + bc]);
            }
            #pragma unroll
            for (int k = 0; k < 8; k++) {
                float a[4];
                *(float4*)&a[0] = *(const float4*)&As[cur][k][tr * 4];
                ulonglong2 q0 = *(const ulonglong2*)&Bs[cur][k][tc * 8];
                ulonglong2 q1 = *(const ulonglong2*)&Bs[cur][k][tc * 8 + 4];
                u64 a2[4];
                #pragma unroll
                for (int i = 0; i < 4; i++) PACK2(a2[i], a[i]);
                #pragma unroll
                for (int i = 0; i < 4; i++) {
                    FFMA2(acc2[i][0], a2[i], q0.x);
                    FFMA2(acc2[i][1], a2[i], q0.y);
                    FFMA2(acc2[i][2], a2[i], q1.x);
                    FFMA2(acc2[i][3], a2[i], q1.y);
                }
            }
            if (kb < 31) {
                const int nxt = cur ^ 1;
                if (tid < 128) {
                    As[nxt][lq + 0][lm] = va_n.x; As[nxt][lq + 1][lm] = va_n.y;
                    As[nxt][lq + 2][lm] = va_n.z; As[nxt][lq + 3][lm] = va_n.w;
                }
                *(float4*)&Bs[nxt][br][bc] = vb_n;
                __syncthreads();
            }
        }
        __syncthreads();   // protect ws/fs reuse across sub iterations

        // Epilogue. Logit lanes: tc<8 <=> warp lanes {0-7,16-23}; mask 0x00FF00FF.
        if (tc < 8) {
            #pragma unroll
            for (int i = 0; i < 4; i++) {
                float v[8];
                #pragma unroll
                for (int jp = 0; jp < 4; jp++)
                    UNPACK2(v[2 * jp], v[2 * jp + 1], acc2[i][jp]);
                float mx = -1e30f;
                #pragma unroll
                for (int j = 0; j < 8; j++) {
                    v[j] = (v[j] + bias[j]) * inv;
                    mx = fmaxf(mx, v[j]);
                }
                mx = fmaxf(mx, __shfl_xor_sync(0x00FF00FFu, mx, 1));
                mx = fmaxf(mx, __shfl_xor_sync(0x00FF00FFu, mx, 2));
                mx = fmaxf(mx, __shfl_xor_sync(0x00FF00FFu, mx, 4));
                float sum = 0.f;
                #pragma unroll
                for (int j = 0; j < 8; j++) {
                    v[j] = __expf(v[j] - mx);
                    sum += v[j];
                }
                sum += __shfl_xor_sync(0x00FF00FFu, sum, 1);
                sum += __shfl_xor_sync(0x00FF00FFu, sum, 2);
                sum += __shfl_xor_sync(0x00FF00FFu, sum, 4);
                const float rs = 1.0f / sum;
                float* dst = &ws[tr * 4 + i][tc * 8];
                *(float4*)(dst + 0) = make_float4(v[0]*rs, v[1]*rs, v[2]*rs, v[3]*rs);
                *(float4*)(dst + 4) = make_float4(v[4]*rs, v[5]*rs, v[6]*rs, v[7]*rs);
            }
        } else {
            #pragma unroll
            for (int i = 0; i < 4; i++) {
                float v[8];
                #pragma unroll
                for (int jp = 0; jp < 4; jp++)
                    UNPACK2(v[2 * jp], v[2 * jp + 1], acc2[i][jp]);
                float* dst = &fs[tr * 4 + i][(tc - 8) * 8];
                *(float4*)(dst + 0) = make_float4(v[0]+bias[0], v[1]+bias[1],
                                                  v[2]+bias[2], v[3]+bias[3]);
                *(float4*)(dst + 4) = make_float4(v[4]+bias[4], v[5]+bias[5],
                                                  v[6]+bias[6], v[7]+bias[7]);
            }
        }
        __syncthreads();

        // Aggregate: M[s][d] += sum_n ws[n][s] * fs[n][d]
        #pragma unroll 4
        for (int n = 0; n < 64; n++) {
            float a[4];
            *(float4*)&a[0] = *(const float4*)&ws[n][tr * 4];
            ulonglong2 fq = *(const ulonglong2*)&fs[n][tc * 4];
            if (tc == 0) {
                nacc[0] += a[0]; nacc[1] += a[1];
                nacc[2] += a[2]; nacc[3] += a[3];
            }
            u64 a2[4];
            #pragma unroll
            for (int u = 0; u < 4; u++) PACK2(a2[u], a[u]);
            #pragma unroll
            for (int u = 0; u < 4; u++) {
                FFMA2(agg2[u][0], a2[u], fq.x);
                FFMA2(agg2[u][1], a2[u], fq.y);
            }
        }
        __syncthreads();
    }

    float* Mp = &g_Mp[((size_t)tb * HEADS + h) * 4096];
    #pragma unroll
    for (int u = 0; u < 4; u++) {
        float r[4];
        UNPACK2(r[0], r[1], agg2[u][0]);
        UNPACK2(r[2], r[3], agg2[u][1]);
        *(float4*)&Mp[(tr * 4 + u) * 64 + tc * 4] = make_float4(r[0], r[1], r[2], r[3]);
    }
    if (tc == 0) {
        float* Np = &g_Np[(tb * HEADS + h) * 64];
        #pragma unroll
        for (int u = 0; u < 4; u++) Np[tr * 4 + u] = nacc[u];
    }
}

// ---------------------------------------------------------------------------
// K3: reduce the 128 per-batch token-block partials, divide by (mass + 0.01).
// ---------------------------------------------------------------------------
__global__ __launch_bounds__(256) void k_final(float* __restrict__ out)
{
    int i = blockIdx.x * 256 + threadIdx.x;    // ((b*8+h)*64+s)*64+d
    int bh = i >> 12;
    int b = bh >> 3, h = bh & 7;
    int s = (i >> 6) & 63;
    float m = 0.f, nn = 0.f;
    for (int t = 0; t < 128; t++) {
        size_t base = (size_t)(b * 128 + t) * HEADS + h;
        m  += g_Mp[base * 4096 + (i & 4095)];
        nn += g_Np[base * 64 + s];
    }
    out[i] = m / (nn + 0.01f);
}

// ---------------------------------------------------------------------------
extern "C" void kernel_launch(void* const* d_in, const int* in_sizes, int n_in,
                              void* d_out, int out_size)
{
    const float* x    = (const float*)d_in[0];
    const float* Wx   = (const float*)d_in[1];
    const float* bx   = (const float*)d_in[2];
    const float* Wfx  = (const float*)d_in[3];
    const float* bfx  = (const float*)d_in[4];
    const float* Ws   = (const float*)d_in[5];
    const float* bs   = (const float*)d_in[6];
    const float* temp = (const float*)d_in[7];
    (void)in_sizes; (void)n_in; (void)out_size;

    k_fold<<<1024, 256>>>(Wx, bx, Wfx, bfx, Ws, bs);
    k_main<<<dim3(HEADS, NTB), 256>>>(x, temp);
    k_final<<<256, 256>>>((float*)d_out);
}